// round 3
// baseline (speedup 1.0000x reference)
#include <cuda_runtime.h>
#include <math.h>

#define Nn 100000
#define Ee 1600000
#define Gg 128
#define IND 329
#define HC  256
#define NB_SCAN 98   // ceil(100000/1024)

// ---------------- device scratch (no allocations allowed) ----------------
__device__ __align__(16) float g_xp[Nn * HC];   // [N, H*C] projected features (102.4 MB)
__device__ __align__(16) float g_asrc[Nn * 4];  // [N, H]
__device__ __align__(16) float g_adst[Nn * 4];  // [N, H]
__device__ __align__(16) float g_h[Nn * 64];    // [N, C] node output after head-mean+relu
__device__ int   g_deg[Nn];            // dst degree / cursor (reused)
__device__ int   g_off[Nn + 1];        // CSR offsets by dst
__device__ int   g_srcs[Ee];           // src ids grouped by dst
__device__ int   g_bsums[128];         // scan block sums
__device__ int   g_gcnt[Gg];
__device__ int   g_goff[Gg + 1];

__device__ __forceinline__ float lrelu(float v) { return v > 0.f ? v : 0.2f * v; }

// ---------------- K1: xp = x @ W  (fp32, 64x256 tile) ----------------
__global__ void gemm_kernel(const float* __restrict__ x, const float* __restrict__ W) {
    __shared__ __align__(16) float As[8][64];
    __shared__ __align__(16) float Bs[8][256];
    int tid = threadIdx.x;            // 256 threads
    int tx = tid & 15, ty = tid >> 4; // 16x16 thread grid
    int m0 = blockIdx.x * 64;

    float acc[4][16];
#pragma unroll
    for (int r = 0; r < 4; r++)
#pragma unroll
        for (int c = 0; c < 16; c++) acc[r][c] = 0.f;

    for (int k0 = 0; k0 < IND; k0 += 8) {
#pragma unroll
        for (int i = 0; i < 2; i++) {
            int idx = tid * 2 + i;
            int m = idx >> 3, kk = idx & 7;
            int gm = m0 + m, gk = k0 + kk;
            As[kk][m] = (gm < Nn && gk < IND) ? x[gm * IND + gk] : 0.f;
        }
#pragma unroll
        for (int i = 0; i < 8; i++) {
            int gk = k0 + i;
            Bs[i][tid] = (gk < IND) ? W[gk * HC + tid] : 0.f;
        }
        __syncthreads();
#pragma unroll
        for (int kk = 0; kk < 8; kk++) {
            float4 a4 = *(const float4*)&As[kk][ty * 4];
            float av[4] = {a4.x, a4.y, a4.z, a4.w};
            float bv[16];
            float4 b4;
            b4 = *(const float4*)&Bs[kk][tx * 16 + 0];  bv[0]=b4.x; bv[1]=b4.y; bv[2]=b4.z; bv[3]=b4.w;
            b4 = *(const float4*)&Bs[kk][tx * 16 + 4];  bv[4]=b4.x; bv[5]=b4.y; bv[6]=b4.z; bv[7]=b4.w;
            b4 = *(const float4*)&Bs[kk][tx * 16 + 8];  bv[8]=b4.x; bv[9]=b4.y; bv[10]=b4.z; bv[11]=b4.w;
            b4 = *(const float4*)&Bs[kk][tx * 16 + 12]; bv[12]=b4.x; bv[13]=b4.y; bv[14]=b4.z; bv[15]=b4.w;
#pragma unroll
            for (int r = 0; r < 4; r++)
#pragma unroll
                for (int c = 0; c < 16; c++)
                    acc[r][c] = fmaf(av[r], bv[c], acc[r][c]);
        }
        __syncthreads();
    }
#pragma unroll
    for (int r = 0; r < 4; r++) {
        int gm = m0 + ty * 4 + r;
        if (gm < Nn) {
            float4* o = (float4*)&g_xp[gm * HC + tx * 16];
            o[0] = make_float4(acc[r][0], acc[r][1], acc[r][2], acc[r][3]);
            o[1] = make_float4(acc[r][4], acc[r][5], acc[r][6], acc[r][7]);
            o[2] = make_float4(acc[r][8], acc[r][9], acc[r][10], acc[r][11]);
            o[3] = make_float4(acc[r][12], acc[r][13], acc[r][14], acc[r][15]);
        }
    }
}

// ---------------- K2: per-node attention dots (warp per node) ----------------
__global__ void attn_kernel(const float* __restrict__ att_src, const float* __restrict__ att_dst) {
    int gw = (blockIdx.x * blockDim.x + threadIdx.x) >> 5;
    int lane = threadIdx.x & 31;
    if (gw >= Nn) return;
    const float4* xp4 = (const float4*)g_xp;
    float4 v0 = xp4[gw * 64 + lane * 2];
    float4 v1 = xp4[gw * 64 + lane * 2 + 1];
    const float4* as4 = (const float4*)att_src;
    const float4* ad4 = (const float4*)att_dst;
    float4 s0 = as4[lane * 2], s1 = as4[lane * 2 + 1];
    float4 d0 = ad4[lane * 2], d1 = ad4[lane * 2 + 1];
    float ps = v0.x*s0.x + v0.y*s0.y + v0.z*s0.z + v0.w*s0.w
             + v1.x*s1.x + v1.y*s1.y + v1.z*s1.z + v1.w*s1.w;
    float pd = v0.x*d0.x + v0.y*d0.y + v0.z*d0.z + v0.w*d0.w
             + v1.x*d1.x + v1.y*d1.y + v1.z*d1.z + v1.w*d1.w;
#pragma unroll
    for (int o = 1; o < 8; o <<= 1) {
        ps += __shfl_xor_sync(0xffffffffu, ps, o);
        pd += __shfl_xor_sync(0xffffffffu, pd, o);
    }
    if ((lane & 7) == 0) {
        g_asrc[gw * 4 + (lane >> 3)] = ps;
        g_adst[gw * 4 + (lane >> 3)] = pd;
    }
}

// ---------------- CSR build ----------------
__global__ void zero1_kernel() {
    int i = blockIdx.x * blockDim.x + threadIdx.x;
    if (i < Nn) g_deg[i] = 0;
    if (i < Gg) g_gcnt[i] = 0;
}
__global__ void count_kernel(const int* __restrict__ ei) {
    int e = blockIdx.x * blockDim.x + threadIdx.x;
    if (e >= Ee) return;
    int dst = ei[Ee + e];
    atomicAdd(&g_deg[dst], 1);
}
__global__ void scan1_kernel() {
    __shared__ int sm[1024];
    int i = blockIdx.x * 1024 + threadIdx.x;
    sm[threadIdx.x] = (i < Nn) ? g_deg[i] : 0;
    __syncthreads();
    for (int o = 512; o > 0; o >>= 1) {
        if (threadIdx.x < o) sm[threadIdx.x] += sm[threadIdx.x + o];
        __syncthreads();
    }
    if (threadIdx.x == 0) g_bsums[blockIdx.x] = sm[0];
}
__global__ void scan2_kernel() {
    if (threadIdx.x == 0) {
        int run = 0;
        for (int b = 0; b < NB_SCAN; b++) { int t = g_bsums[b]; g_bsums[b] = run; run += t; }
        g_off[Nn] = run;
    }
}
__global__ void scan3_kernel() {
    __shared__ int sm[1024];
    int i = blockIdx.x * 1024 + threadIdx.x;
    int v = (i < Nn) ? g_deg[i] : 0;
    sm[threadIdx.x] = v;
    __syncthreads();
    for (int o = 1; o < 1024; o <<= 1) {
        int t = (threadIdx.x >= o) ? sm[threadIdx.x - o] : 0;
        __syncthreads();
        sm[threadIdx.x] += t;
        __syncthreads();
    }
    if (i < Nn) g_off[i] = g_bsums[blockIdx.x] + sm[threadIdx.x] - v;
}
__global__ void zero2_kernel() {
    int i = blockIdx.x * blockDim.x + threadIdx.x;
    if (i < Nn) g_deg[i] = 0;
}
__global__ void fill_kernel(const int* __restrict__ ei) {
    int e = blockIdx.x * blockDim.x + threadIdx.x;
    if (e >= Ee) return;
    int src = ei[e];
    int dst = ei[Ee + e];
    int pos = g_off[dst] + atomicAdd(&g_deg[dst], 1);
    g_srcs[pos] = src;
}

// ---------------- K3: GAT aggregation, warp per destination ----------------
__global__ void gat_kernel(const float* __restrict__ bias) {
    int gw = (blockIdx.x * blockDim.x + threadIdx.x) >> 5;
    int lane = threadIdx.x & 31;
    if (gw >= Nn) return;
    int d = gw;
    int beg = g_off[d], end = g_off[d + 1];
    const float4* asrc4 = (const float4*)g_asrc;

    float4 adv = ((const float4*)g_adst)[d];
    float ad[4] = {adv.x, adv.y, adv.z, adv.w};
    float4 sv = asrc4[d];
    float slf[4];
    slf[0] = lrelu(sv.x + ad[0]); slf[1] = lrelu(sv.y + ad[1]);
    slf[2] = lrelu(sv.z + ad[2]); slf[3] = lrelu(sv.w + ad[3]);

    // pass 1: segment max (self loop included)
    float mx[4] = {slf[0], slf[1], slf[2], slf[3]};
    for (int e = beg + lane; e < end; e += 32) {
        int s = g_srcs[e];
        float4 a = asrc4[s];
        mx[0] = fmaxf(mx[0], lrelu(a.x + ad[0]));
        mx[1] = fmaxf(mx[1], lrelu(a.y + ad[1]));
        mx[2] = fmaxf(mx[2], lrelu(a.z + ad[2]));
        mx[3] = fmaxf(mx[3], lrelu(a.w + ad[3]));
    }
#pragma unroll
    for (int o = 16; o > 0; o >>= 1) {
#pragma unroll
        for (int h = 0; h < 4; h++)
            mx[h] = fmaxf(mx[h], __shfl_xor_sync(0xffffffffu, mx[h], o));
    }

    // pass 2: denom
    float den[4];
#pragma unroll
    for (int h = 0; h < 4; h++) den[h] = (lane == 0) ? __expf(slf[h] - mx[h]) : 0.f;
    for (int e = beg + lane; e < end; e += 32) {
        int s = g_srcs[e];
        float4 a = asrc4[s];
        den[0] += __expf(lrelu(a.x + ad[0]) - mx[0]);
        den[1] += __expf(lrelu(a.y + ad[1]) - mx[1]);
        den[2] += __expf(lrelu(a.z + ad[2]) - mx[2]);
        den[3] += __expf(lrelu(a.w + ad[3]) - mx[3]);
    }
#pragma unroll
    for (int o = 16; o > 0; o >>= 1) {
#pragma unroll
        for (int h = 0; h < 4; h++)
            den[h] += __shfl_xor_sync(0xffffffffu, den[h], o);
    }
    float rden[4];
#pragma unroll
    for (int h = 0; h < 4; h++) rden[h] = 1.f / den[h];

    // pass 3: weighted gather-accumulate. lane covers flat idx [lane*8, lane*8+8)
    int hm = lane >> 3;                 // this lane's head
    float myad = ad[hm], mymx = mx[hm], myrd = rden[hm];
    float acc[8] = {0, 0, 0, 0, 0, 0, 0, 0};
    const float4* xp4 = (const float4*)g_xp;

    // self loop
    {
        float alpha = __expf(slf[hm] - mymx) * myrd;
        float4 v0 = xp4[d * 64 + lane * 2];
        float4 v1 = xp4[d * 64 + lane * 2 + 1];
        acc[0] += alpha * v0.x; acc[1] += alpha * v0.y; acc[2] += alpha * v0.z; acc[3] += alpha * v0.w;
        acc[4] += alpha * v1.x; acc[5] += alpha * v1.y; acc[6] += alpha * v1.z; acc[7] += alpha * v1.w;
    }
    int e = beg;
    int sn = (e < end) ? g_srcs[e] : 0;
    while (e < end) {
        int s = sn;
        e++;
        if (e < end) sn = g_srcs[e];          // prefetch next src
        float ah = g_asrc[s * 4 + hm];
        float alpha = __expf(lrelu(ah + myad) - mymx) * myrd;
        float4 v0 = xp4[s * 64 + lane * 2];
        float4 v1 = xp4[s * 64 + lane * 2 + 1];
        acc[0] += alpha * v0.x; acc[1] += alpha * v0.y; acc[2] += alpha * v0.z; acc[3] += alpha * v0.w;
        acc[4] += alpha * v1.x; acc[5] += alpha * v1.y; acc[6] += alpha * v1.z; acc[7] += alpha * v1.w;
    }
    // reduce over heads (lanes L, L^8, L^16, L^24 share the same columns)
#pragma unroll
    for (int j = 0; j < 8; j++) {
        acc[j] += __shfl_xor_sync(0xffffffffu, acc[j], 8);
        acc[j] += __shfl_xor_sync(0xffffffffu, acc[j], 16);
    }
    if (lane < 8) {
        float o[8];
#pragma unroll
        for (int j = 0; j < 8; j++)
            o[j] = fmaxf(acc[j] * 0.25f + bias[lane * 8 + j], 0.f);
        float4* hp = (float4*)&g_h[d * 64 + lane * 8];
        hp[0] = make_float4(o[0], o[1], o[2], o[3]);
        hp[1] = make_float4(o[4], o[5], o[6], o[7]);
    }
}

// ---------------- pool + MLP ----------------
__global__ void gcount_kernel(const int* __restrict__ batch) {
    int i = blockIdx.x * blockDim.x + threadIdx.x;
    if (i < Nn) atomicAdd(&g_gcnt[batch[i]], 1);
}
__global__ void gscan_kernel() {
    if (threadIdx.x == 0) {
        int run = 0;
        for (int b = 0; b < Gg; b++) { g_goff[b] = run; run += g_gcnt[b]; }
        g_goff[Gg] = run;
    }
}
__global__ void pool_mlp_kernel(const float* __restrict__ w1, const float* __restrict__ b1,
                                const float* __restrict__ w2, const float* __restrict__ b2,
                                float* __restrict__ y) {
    __shared__ float sg[64];
    __shared__ float red[256];
    int b = blockIdx.x;
    int tid = threadIdx.x;
    int col = tid & 63, grp = tid >> 6;
    int s0 = g_goff[b], s1 = g_goff[b + 1];
    float sum = 0.f;
    for (int r = s0 + grp; r < s1; r += 4) sum += g_h[r * 64 + col];
    red[tid] = sum;
    __syncthreads();
    if (grp == 0) {
        float tot = red[col] + red[col + 64] + red[col + 128] + red[col + 192];
        float cnt = (float)((s1 - s0) > 1 ? (s1 - s0) : 1);
        sg[col] = tot / cnt;
    }
    __syncthreads();
    float part = 0.f;
    if (tid < 64) {
        float hsum = b1[tid];
#pragma unroll
        for (int c = 0; c < 64; c++) hsum = fmaf(sg[c], w1[c * 64 + tid], hsum);
        part = fmaxf(hsum, 0.f) * w2[tid];
    }
    red[tid] = part;
    __syncthreads();
    if (tid == 0) {
        float s = b2[0];
        for (int j = 0; j < 64; j++) s += red[j];
        y[b] = 1.f / (1.f + __expf(-s));
    }
}

// ---------------- launch ----------------
extern "C" void kernel_launch(void* const* d_in, const int* in_sizes, int n_in,
                              void* d_out, int out_size) {
    const float* x       = (const float*)d_in[0];
    const float* W       = (const float*)d_in[1];
    const float* att_src = (const float*)d_in[2];
    const float* att_dst = (const float*)d_in[3];
    const float* bias    = (const float*)d_in[4];
    const float* w1      = (const float*)d_in[5];
    const float* b1      = (const float*)d_in[6];
    const float* w2      = (const float*)d_in[7];
    const float* b2      = (const float*)d_in[8];
    const int* ei        = (const int*)d_in[9];
    const int* batch     = (const int*)d_in[10];
    float* y = (float*)d_out;

    gemm_kernel<<<(Nn + 63) / 64, 256>>>(x, W);
    attn_kernel<<<(Nn * 32 + 255) / 256, 256>>>(att_src, att_dst);
    zero1_kernel<<<(Nn + 255) / 256, 256>>>();
    count_kernel<<<(Ee + 255) / 256, 256>>>(ei);
    scan1_kernel<<<NB_SCAN, 1024>>>();
    scan2_kernel<<<1, 32>>>();
    scan3_kernel<<<NB_SCAN, 1024>>>();
    zero2_kernel<<<(Nn + 255) / 256, 256>>>();
    fill_kernel<<<(Ee + 255) / 256, 256>>>(ei);
    gat_kernel<<<(Nn * 32 + 255) / 256, 256>>>(bias);
    gcount_kernel<<<(Nn + 255) / 256, 256>>>(batch);
    gscan_kernel<<<1, 32>>>();
    pool_mlp_kernel<<<Gg, 256>>>(w1, b1, w2, b2, y);
}

// round 8
// speedup vs baseline: 3.4203x; 3.4203x over previous
#include <cuda_runtime.h>
#include <cuda_fp16.h>
#include <cstdint>
#include <math.h>

#define Nn 100000
#define Ee 1600000
#define Gg 128
#define IND 329
#define HC  256
#define KPAD 336          // IND padded to multiple of 16
#define NB_SCAN 98        // ceil(100000/1024)

// ---------------- device scratch (no allocations allowed) ----------------
__device__ __align__(16) __half g_xph[Nn * HC];   // [N,256] projected features fp16 (51.2 MB)
__device__ __align__(16) float  g_wt[KPAD * HC];  // W in tf32-rounded f32, zero-padded rows
__device__ __align__(16) float  g_asrc[Nn * 4];   // [N,H] fp32
__device__ __align__(16) float  g_adst[Nn * 4];   // [N,H] fp32
__device__ __align__(16) float  g_h[Nn * 64];     // [N,C]
__device__ int   g_deg[Nn];
__device__ int   g_off[Nn + 1];
__device__ int   g_srcs[Ee];
__device__ int   g_bsums[128];
__device__ int   g_gcnt[Gg];
__device__ int   g_goff[Gg + 1];

__device__ __forceinline__ float lrelu(float v) { return v > 0.f ? v : 0.2f * v; }

__device__ __forceinline__ uint32_t f2tf32(float v) {
    uint32_t u;
    asm("cvt.rna.tf32.f32 %0, %1;" : "=r"(u) : "f"(v));
    return u;
}

__device__ __forceinline__ void mma_tf32(float c[4], const uint32_t a[4], uint32_t b0, uint32_t b1) {
    asm volatile(
        "mma.sync.aligned.m16n8k8.row.col.f32.tf32.tf32.f32 "
        "{%0,%1,%2,%3}, {%4,%5,%6,%7}, {%8,%9}, {%0,%1,%2,%3};\n"
        : "+f"(c[0]), "+f"(c[1]), "+f"(c[2]), "+f"(c[3])
        : "r"(a[0]), "r"(a[1]), "r"(a[2]), "r"(a[3]), "r"(b0), "r"(b1));
}

// ---------------- K0: W -> tf32-rounded f32, padded to [KPAD][256] ----------------
__global__ void cvt_w_kernel(const float* __restrict__ W) {
    int r = blockIdx.x, c = threadIdx.x;   // grid KPAD, block 256
    float v = (r < IND) ? W[r * HC + c] : 0.f;
    g_wt[r * HC + c] = __uint_as_float(f2tf32(v));
}

// ---------------- K1: xp = x@W via tf32 HMMA; fused att dots; fp16 out -------
// Tile: BM=128, BN=128, BK=16. 256 threads = 8 warps (4 m x 2 n). Warp tile 32x64.
__global__ void __launch_bounds__(256, 2)
gemm_kernel(const float* __restrict__ x,
            const float* __restrict__ att_src, const float* __restrict__ att_dst) {
    __shared__ float As[128 * 20];   // row stride 20 (pad) - bank-conflict free frag loads
    __shared__ float Bs[16 * 136];   // row stride 136
    __shared__ float att_s[128], att_d[128];

    const int tid = threadIdx.x;
    const int lane = tid & 31, wid = tid >> 5;
    const int wm = wid & 3, wn = wid >> 2;      // warp rows wm*32, cols wn*64
    const int gy = lane >> 2, gx = lane & 3;
    const int m0 = blockIdx.x * 128;
    const int nblk = blockIdx.y * 128;

    if (tid < 128) {
        att_s[tid] = att_src[nblk + tid];
        att_d[tid] = att_dst[nblk + tid];
    }

    float acc[2][8][4];
#pragma unroll
    for (int mf = 0; mf < 2; mf++)
#pragma unroll
        for (int nf = 0; nf < 8; nf++)
#pragma unroll
            for (int i = 0; i < 4; i++) acc[mf][nf][i] = 0.f;

    for (int k0 = 0; k0 < KPAD; k0 += 16) {
        // fill A: 128x16 f32, cvt to tf32 in transit
#pragma unroll
        for (int j = 0; j < 8; j++) {
            int e = tid + j * 256;
            int row = e >> 4, col = e & 15;
            int gm = m0 + row, gk = k0 + col;
            float v = (gm < Nn && gk < IND) ? x[gm * IND + gk] : 0.f;
            As[row * 20 + col] = __uint_as_float(f2tf32(v));
        }
        // fill B: 16x128 from pre-converted g_wt
#pragma unroll
        for (int j = 0; j < 2; j++) {
            int idx = tid + j * 256;
            int kr = idx >> 5, seg = idx & 31;
            float4 v = *(const float4*)&g_wt[(k0 + kr) * HC + nblk + seg * 4];
            *(float4*)&Bs[kr * 136 + seg * 4] = v;
        }
        __syncthreads();
#pragma unroll
        for (int h8 = 0; h8 < 2; h8++) {
            uint32_t a[2][4];
#pragma unroll
            for (int mf = 0; mf < 2; mf++) {
                int r = wm * 32 + mf * 16 + gy;
                a[mf][0] = __float_as_uint(As[r * 20 + h8 * 8 + gx]);
                a[mf][1] = __float_as_uint(As[(r + 8) * 20 + h8 * 8 + gx]);
                a[mf][2] = __float_as_uint(As[r * 20 + h8 * 8 + gx + 4]);
                a[mf][3] = __float_as_uint(As[(r + 8) * 20 + h8 * 8 + gx + 4]);
            }
#pragma unroll
            for (int nf = 0; nf < 8; nf++) {
                int n = wn * 64 + nf * 8 + gy;
                uint32_t b0 = __float_as_uint(Bs[(h8 * 8 + gx) * 136 + n]);
                uint32_t b1 = __float_as_uint(Bs[(h8 * 8 + gx + 4) * 136 + n]);
                mma_tf32(acc[0][nf], a[0], b0, b1);
                mma_tf32(acc[1][nf], a[1], b0, b1);
            }
        }
        __syncthreads();
    }

    // epilogue: store xp as half2, accumulate att dots in fp32
    float sdS[2][2] = {{0, 0}, {0, 0}};   // [mf][row half]
    float sdD[2][2] = {{0, 0}, {0, 0}};
#pragma unroll
    for (int mf = 0; mf < 2; mf++) {
        int row_l = wm * 32 + mf * 16 + gy;
        int gm = m0 + row_l;
#pragma unroll
        for (int nf = 0; nf < 8; nf++) {
            int col_l = wn * 64 + nf * 8 + gx * 2;
            float c0 = acc[mf][nf][0], c1 = acc[mf][nf][1];
            float c2 = acc[mf][nf][2], c3 = acc[mf][nf][3];
            float as0 = att_s[col_l], as1 = att_s[col_l + 1];
            float ad0 = att_d[col_l], ad1 = att_d[col_l + 1];
            sdS[mf][0] += c0 * as0 + c1 * as1;
            sdS[mf][1] += c2 * as0 + c3 * as1;
            sdD[mf][0] += c0 * ad0 + c1 * ad1;
            sdD[mf][1] += c2 * ad0 + c3 * ad1;
            int gcol = nblk + col_l;
            if (gm < Nn)
                *(__half2*)&g_xph[(size_t)gm * HC + gcol] = __floats2half2_rn(c0, c1);
            if (gm + 8 < Nn)
                *(__half2*)&g_xph[(size_t)(gm + 8) * HC + gcol] = __floats2half2_rn(c2, c3);
        }
    }
    // reduce dot partials across the 4 lanes sharing a row (gx axis)
#pragma unroll
    for (int o = 1; o < 4; o <<= 1) {
#pragma unroll
        for (int mf = 0; mf < 2; mf++)
#pragma unroll
            for (int rr = 0; rr < 2; rr++) {
                sdS[mf][rr] += __shfl_xor_sync(0xffffffffu, sdS[mf][rr], o);
                sdD[mf][rr] += __shfl_xor_sync(0xffffffffu, sdD[mf][rr], o);
            }
    }
    if (gx == 0) {
        int head = blockIdx.y * 2 + wn;
#pragma unroll
        for (int mf = 0; mf < 2; mf++)
#pragma unroll
            for (int rr = 0; rr < 2; rr++) {
                int gm = m0 + wm * 32 + mf * 16 + gy + rr * 8;
                if (gm < Nn) {
                    g_asrc[gm * 4 + head] = sdS[mf][rr];
                    g_adst[gm * 4 + head] = sdD[mf][rr];
                }
            }
    }
}

// ---------------- CSR build ----------------
__global__ void zero1_kernel() {
    int i = blockIdx.x * blockDim.x + threadIdx.x;
    if (i < Nn) g_deg[i] = 0;
    if (i < Gg) g_gcnt[i] = 0;
}
__global__ void count_kernel(const int* __restrict__ ei) {
    int e = blockIdx.x * blockDim.x + threadIdx.x;
    if (e >= Ee) return;
    atomicAdd(&g_deg[ei[Ee + e]], 1);
}
__global__ void scan1_kernel() {
    __shared__ int sm[1024];
    int i = blockIdx.x * 1024 + threadIdx.x;
    sm[threadIdx.x] = (i < Nn) ? g_deg[i] : 0;
    __syncthreads();
    for (int o = 512; o > 0; o >>= 1) {
        if (threadIdx.x < o) sm[threadIdx.x] += sm[threadIdx.x + o];
        __syncthreads();
    }
    if (threadIdx.x == 0) g_bsums[blockIdx.x] = sm[0];
}
__global__ void scan2_kernel() {
    if (threadIdx.x == 0) {
        int run = 0;
        for (int b = 0; b < NB_SCAN; b++) { int t = g_bsums[b]; g_bsums[b] = run; run += t; }
        g_off[Nn] = run;
    }
}
__global__ void scan3_kernel() {
    __shared__ int sm[1024];
    int i = blockIdx.x * 1024 + threadIdx.x;
    int v = (i < Nn) ? g_deg[i] : 0;
    sm[threadIdx.x] = v;
    __syncthreads();
    for (int o = 1; o < 1024; o <<= 1) {
        int t = (threadIdx.x >= o) ? sm[threadIdx.x - o] : 0;
        __syncthreads();
        sm[threadIdx.x] += t;
        __syncthreads();
    }
    if (i < Nn) g_off[i] = g_bsums[blockIdx.x] + sm[threadIdx.x] - v;
}
__global__ void zero2_kernel() {
    int i = blockIdx.x * blockDim.x + threadIdx.x;
    if (i < Nn) g_deg[i] = 0;
}
__global__ void fill_kernel(const int* __restrict__ ei) {
    int e = blockIdx.x * blockDim.x + threadIdx.x;
    if (e >= Ee) return;
    int src = ei[e];
    int dst = ei[Ee + e];
    int pos = g_off[dst] + atomicAdd(&g_deg[dst], 1);
    g_srcs[pos] = src;
}

// ---------------- K3: GAT aggregation, warp per destination (half gather) ----
__global__ void gat_kernel(const float* __restrict__ bias) {
    int gw = (blockIdx.x * blockDim.x + threadIdx.x) >> 5;
    int lane = threadIdx.x & 31;
    if (gw >= Nn) return;
    int d = gw;
    int beg = g_off[d], end = g_off[d + 1];
    const float4* asrc4 = (const float4*)g_asrc;

    float4 adv = ((const float4*)g_adst)[d];
    float ad[4] = {adv.x, adv.y, adv.z, adv.w};
    float4 sv = asrc4[d];
    float slf[4];
    slf[0] = lrelu(sv.x + ad[0]); slf[1] = lrelu(sv.y + ad[1]);
    slf[2] = lrelu(sv.z + ad[2]); slf[3] = lrelu(sv.w + ad[3]);

    // pass 1: segment max
    float mx[4] = {slf[0], slf[1], slf[2], slf[3]};
    for (int e = beg + lane; e < end; e += 32) {
        int s = g_srcs[e];
        float4 a = asrc4[s];
        mx[0] = fmaxf(mx[0], lrelu(a.x + ad[0]));
        mx[1] = fmaxf(mx[1], lrelu(a.y + ad[1]));
        mx[2] = fmaxf(mx[2], lrelu(a.z + ad[2]));
        mx[3] = fmaxf(mx[3], lrelu(a.w + ad[3]));
    }
#pragma unroll
    for (int o = 16; o > 0; o >>= 1)
#pragma unroll
        for (int h = 0; h < 4; h++)
            mx[h] = fmaxf(mx[h], __shfl_xor_sync(0xffffffffu, mx[h], o));

    // pass 2: denom
    float den[4];
#pragma unroll
    for (int h = 0; h < 4; h++) den[h] = (lane == 0) ? __expf(slf[h] - mx[h]) : 0.f;
    for (int e = beg + lane; e < end; e += 32) {
        int s = g_srcs[e];
        float4 a = asrc4[s];
        den[0] += __expf(lrelu(a.x + ad[0]) - mx[0]);
        den[1] += __expf(lrelu(a.y + ad[1]) - mx[1]);
        den[2] += __expf(lrelu(a.z + ad[2]) - mx[2]);
        den[3] += __expf(lrelu(a.w + ad[3]) - mx[3]);
    }
#pragma unroll
    for (int o = 16; o > 0; o >>= 1)
#pragma unroll
        for (int h = 0; h < 4; h++)
            den[h] += __shfl_xor_sync(0xffffffffu, den[h], o);
    float rden[4];
#pragma unroll
    for (int h = 0; h < 4; h++) rden[h] = 1.f / den[h];

    // pass 3: fp16 gather. lane covers cols [lane*8, lane*8+8); head = lane>>3
    int hm = lane >> 3;
    float myad = ad[hm], mymx = mx[hm], myrd = rden[hm];
    float acc[8] = {0, 0, 0, 0, 0, 0, 0, 0};

    // self loop
    {
        float alpha = __expf(slf[hm] - mymx) * myrd;
        uint4 v = *(const uint4*)&g_xph[(size_t)d * HC + lane * 8];
        const __half2* hp = (const __half2*)&v;
#pragma unroll
        for (int q = 0; q < 4; q++) {
            float2 f = __half22float2(hp[q]);
            acc[q * 2] += alpha * f.x;
            acc[q * 2 + 1] += alpha * f.y;
        }
    }
    int e = beg;
    int sn = (e < end) ? g_srcs[e] : 0;
    while (e < end) {
        int s = sn;
        e++;
        if (e < end) sn = g_srcs[e];
        float ah = g_asrc[s * 4 + hm];
        float alpha = __expf(lrelu(ah + myad) - mymx) * myrd;
        uint4 v = *(const uint4*)&g_xph[(size_t)s * HC + lane * 8];
        const __half2* hp = (const __half2*)&v;
#pragma unroll
        for (int q = 0; q < 4; q++) {
            float2 f = __half22float2(hp[q]);
            acc[q * 2] += alpha * f.x;
            acc[q * 2 + 1] += alpha * f.y;
        }
    }
    // reduce over heads
#pragma unroll
    for (int j = 0; j < 8; j++) {
        acc[j] += __shfl_xor_sync(0xffffffffu, acc[j], 8);
        acc[j] += __shfl_xor_sync(0xffffffffu, acc[j], 16);
    }
    if (lane < 8) {
        float o[8];
#pragma unroll
        for (int j = 0; j < 8; j++)
            o[j] = fmaxf(acc[j] * 0.25f + bias[lane * 8 + j], 0.f);
        float4* hp = (float4*)&g_h[d * 64 + lane * 8];
        hp[0] = make_float4(o[0], o[1], o[2], o[3]);
        hp[1] = make_float4(o[4], o[5], o[6], o[7]);
    }
}

// ---------------- pool + MLP ----------------
__global__ void gcount_kernel(const int* __restrict__ batch) {
    int i = blockIdx.x * blockDim.x + threadIdx.x;
    if (i < Nn) atomicAdd(&g_gcnt[batch[i]], 1);
}
__global__ void gscan_kernel() {
    if (threadIdx.x == 0) {
        int run = 0;
        for (int b = 0; b < Gg; b++) { g_goff[b] = run; run += g_gcnt[b]; }
        g_goff[Gg] = run;
    }
}
__global__ void pool_mlp_kernel(const float* __restrict__ w1, const float* __restrict__ b1,
                                const float* __restrict__ w2, const float* __restrict__ b2,
                                float* __restrict__ y) {
    __shared__ float sg[64];
    __shared__ float red[256];
    int b = blockIdx.x;
    int tid = threadIdx.x;
    int col = tid & 63, grp = tid >> 6;
    int s0 = g_goff[b], s1 = g_goff[b + 1];
    float sum = 0.f;
    for (int r = s0 + grp; r < s1; r += 4) sum += g_h[r * 64 + col];
    red[tid] = sum;
    __syncthreads();
    if (grp == 0) {
        float tot = red[col] + red[col + 64] + red[col + 128] + red[col + 192];
        float cnt = (float)((s1 - s0) > 1 ? (s1 - s0) : 1);
        sg[col] = tot / cnt;
    }
    __syncthreads();
    float part = 0.f;
    if (tid < 64) {
        float hsum = b1[tid];
#pragma unroll
        for (int c = 0; c < 64; c++) hsum = fmaf(sg[c], w1[c * 64 + tid], hsum);
        part = fmaxf(hsum, 0.f) * w2[tid];
    }
    red[tid] = part;
    __syncthreads();
    if (tid == 0) {
        float s = b2[0];
        for (int j = 0; j < 64; j++) s += red[j];
        y[b] = 1.f / (1.f + __expf(-s));
    }
}

// ---------------- launch ----------------
extern "C" void kernel_launch(void* const* d_in, const int* in_sizes, int n_in,
                              void* d_out, int out_size) {
    const float* x       = (const float*)d_in[0];
    const float* W       = (const float*)d_in[1];
    const float* att_src = (const float*)d_in[2];
    const float* att_dst = (const float*)d_in[3];
    const float* bias    = (const float*)d_in[4];
    const float* w1      = (const float*)d_in[5];
    const float* b1      = (const float*)d_in[6];
    const float* w2      = (const float*)d_in[7];
    const float* b2      = (const float*)d_in[8];
    const int* ei        = (const int*)d_in[9];
    const int* batch     = (const int*)d_in[10];
    float* y = (float*)d_out;

    cvt_w_kernel<<<KPAD, 256>>>(W);
    gemm_kernel<<<dim3((Nn + 127) / 128, 2), 256>>>(x, att_src, att_dst);
    zero1_kernel<<<(Nn + 255) / 256, 256>>>();
    count_kernel<<<(Ee + 255) / 256, 256>>>(ei);
    scan1_kernel<<<NB_SCAN, 1024>>>();
    scan2_kernel<<<1, 32>>>();
    scan3_kernel<<<NB_SCAN, 1024>>>();
    zero2_kernel<<<(Nn + 255) / 256, 256>>>();
    fill_kernel<<<(Ee + 255) / 256, 256>>>(ei);
    gat_kernel<<<(Nn * 32 + 255) / 256, 256>>>(bias);
    gcount_kernel<<<(Nn + 255) / 256, 256>>>(batch);
    gscan_kernel<<<1, 32>>>();
    pool_mlp_kernel<<<Gg, 256>>>(w1, b1, w2, b2, y);
}

// round 14
// speedup vs baseline: 3.5204x; 1.0293x over previous
#include <cuda_runtime.h>
#include <cuda_fp16.h>
#include <cstdint>
#include <math.h>

#define Nn 100000
#define Ee 1600000
#define Gg 128
#define IND 329
#define HC  256
#define KPAD 336          // IND padded to multiple of 16
#define NTILE 21          // KPAD/16
#define NB_SCAN 98        // ceil(100000/1024)

// ---------------- device scratch (no allocations allowed) ----------------
__device__ __align__(16) __half g_xph[Nn * HC];   // [N,256] projected features fp16 (51.2 MB)
__device__ __align__(16) float  g_wt[KPAD * HC];  // W in tf32-rounded f32, zero-padded rows
__device__ __align__(16) float  g_asrc[Nn * 4];   // [N,H] fp32
__device__ __align__(16) float  g_adst[Nn * 4];   // [N,H] fp32
__device__ __align__(16) float  g_h[Nn * 64];     // [N,C]
__device__ int   g_deg[Nn];
__device__ int   g_off[Nn + 1];
__device__ int   g_srcs[Ee];
__device__ int   g_bsums[128];
__device__ int   g_gcnt[Gg];
__device__ int   g_goff[Gg + 1];

__device__ __forceinline__ float lrelu(float v) { return v > 0.f ? v : 0.2f * v; }

__device__ __forceinline__ uint32_t f2tf32(float v) {
    uint32_t u;
    asm("cvt.rna.tf32.f32 %0, %1;" : "=r"(u) : "f"(v));
    return u;
}

__device__ __forceinline__ void mma_tf32(float c[4], const uint32_t a[4], uint32_t b0, uint32_t b1) {
    asm volatile(
        "mma.sync.aligned.m16n8k8.row.col.f32.tf32.tf32.f32 "
        "{%0,%1,%2,%3}, {%4,%5,%6,%7}, {%8,%9}, {%0,%1,%2,%3};\n"
        : "+f"(c[0]), "+f"(c[1]), "+f"(c[2]), "+f"(c[3])
        : "r"(a[0]), "r"(a[1]), "r"(a[2]), "r"(a[3]), "r"(b0), "r"(b1));
}

// ---------------- K0: W -> tf32-rounded f32, padded to [KPAD][256] ----------------
__global__ void cvt_w_kernel(const float* __restrict__ W) {
    int r = blockIdx.x, c = threadIdx.x;   // grid KPAD, block 256
    float v = (r < IND) ? W[r * HC + c] : 0.f;
    g_wt[r * HC + c] = __uint_as_float(f2tf32(v));
}

// ---------------- K1: xp = x@W via tf32 HMMA, BM=128 BN=256, pipelined -------
// 512 threads = 16 warps (4m x 4n). Warp tile 32x64. Single pass over x.
__global__ void __launch_bounds__(512, 1)
gemm_kernel(const float* __restrict__ x,
            const float* __restrict__ att_src, const float* __restrict__ att_dst) {
    __shared__ float As[128 * 20];    // raw f32, stride 20: conflict-free
    __shared__ float Bs[16 * 264];    // tf32-rounded f32, stride 264: conflict-free
    __shared__ float att_s[256], att_d[256];

    const int tid = threadIdx.x;
    const int lane = tid & 31, wid = tid >> 5;
    const int wm = wid & 3, wn = wid >> 2;       // warp rows wm*32, cols wn*64
    const int gy = lane >> 2, gx = lane & 3;
    const int m0 = blockIdx.x * 128;

    if (tid < 256) { att_s[tid] = att_src[tid]; att_d[tid] = att_dst[tid]; }

    float acc[2][8][4];
#pragma unroll
    for (int mf = 0; mf < 2; mf++)
#pragma unroll
        for (int nf = 0; nf < 8; nf++)
#pragma unroll
            for (int i = 0; i < 4; i++) acc[mf][nf][i] = 0.f;

    // ---- prologue: load tile 0 into registers, commit to smem ----
    float aS[4];
    float4 bS[2];
#pragma unroll
    for (int j = 0; j < 4; j++) {
        int e = tid + j * 512;
        int row = e >> 4, col = e & 15;
        int gm = m0 + row;
        aS[j] = (gm < Nn && col < IND) ? x[gm * IND + col] : 0.f;
    }
#pragma unroll
    for (int j = 0; j < 2; j++) {
        int idx = tid + j * 512;
        int kr = idx >> 6, seg = idx & 63;
        bS[j] = *(const float4*)&g_wt[kr * HC + seg * 4];
    }
#pragma unroll
    for (int j = 0; j < 4; j++) {
        int e = tid + j * 512;
        As[(e >> 4) * 20 + (e & 15)] = aS[j];
    }
#pragma unroll
    for (int j = 0; j < 2; j++) {
        int idx = tid + j * 512;
        *(float4*)&Bs[(idx >> 6) * 264 + (idx & 63) * 4] = bS[j];
    }
    __syncthreads();

    for (int t = 1; t <= NTILE; t++) {
        // issue next-tile loads (overlap with MMA below)
        if (t < NTILE) {
            int k0 = t * 16;
#pragma unroll
            for (int j = 0; j < 4; j++) {
                int e = tid + j * 512;
                int row = e >> 4, col = e & 15;
                int gm = m0 + row, gk = k0 + col;
                aS[j] = (gm < Nn && gk < IND) ? x[gm * IND + gk] : 0.f;
            }
#pragma unroll
            for (int j = 0; j < 2; j++) {
                int idx = tid + j * 512;
                int kr = idx >> 6, seg = idx & 63;
                bS[j] = *(const float4*)&g_wt[(k0 + kr) * HC + seg * 4];
            }
        }
        // compute tile t-1 from smem
#pragma unroll
        for (int h8 = 0; h8 < 2; h8++) {
            uint32_t a[2][4];
#pragma unroll
            for (int mf = 0; mf < 2; mf++) {
                int r = wm * 32 + mf * 16 + gy;
                a[mf][0] = f2tf32(As[r * 20 + h8 * 8 + gx]);
                a[mf][1] = f2tf32(As[(r + 8) * 20 + h8 * 8 + gx]);
                a[mf][2] = f2tf32(As[r * 20 + h8 * 8 + gx + 4]);
                a[mf][3] = f2tf32(As[(r + 8) * 20 + h8 * 8 + gx + 4]);
            }
#pragma unroll
            for (int nf = 0; nf < 8; nf++) {
                int n = wn * 64 + nf * 8 + gy;
                uint32_t b0 = __float_as_uint(Bs[(h8 * 8 + gx) * 264 + n]);
                uint32_t b1 = __float_as_uint(Bs[(h8 * 8 + gx + 4) * 264 + n]);
                mma_tf32(acc[0][nf], a[0], b0, b1);
                mma_tf32(acc[1][nf], a[1], b0, b1);
            }
        }
        __syncthreads();
        if (t < NTILE) {
#pragma unroll
            for (int j = 0; j < 4; j++) {
                int e = tid + j * 512;
                As[(e >> 4) * 20 + (e & 15)] = aS[j];
            }
#pragma unroll
            for (int j = 0; j < 2; j++) {
                int idx = tid + j * 512;
                *(float4*)&Bs[(idx >> 6) * 264 + (idx & 63) * 4] = bS[j];
            }
            __syncthreads();
        }
    }

    // ---- epilogue: xp -> fp16; fused att dots (head = wn) ----
    float sdS[2][2] = {{0, 0}, {0, 0}};
    float sdD[2][2] = {{0, 0}, {0, 0}};
#pragma unroll
    for (int mf = 0; mf < 2; mf++) {
        int row_l = wm * 32 + mf * 16 + gy;
        int gm = m0 + row_l;
#pragma unroll
        for (int nf = 0; nf < 8; nf++) {
            int col_l = wn * 64 + nf * 8 + gx * 2;
            float c0 = acc[mf][nf][0], c1 = acc[mf][nf][1];
            float c2 = acc[mf][nf][2], c3 = acc[mf][nf][3];
            float as0 = att_s[col_l], as1 = att_s[col_l + 1];
            float ad0 = att_d[col_l], ad1 = att_d[col_l + 1];
            sdS[mf][0] += c0 * as0 + c1 * as1;
            sdS[mf][1] += c2 * as0 + c3 * as1;
            sdD[mf][0] += c0 * ad0 + c1 * ad1;
            sdD[mf][1] += c2 * ad0 + c3 * ad1;
            if (gm < Nn)
                *(__half2*)&g_xph[(size_t)gm * HC + col_l] = __floats2half2_rn(c0, c1);
            if (gm + 8 < Nn)
                *(__half2*)&g_xph[(size_t)(gm + 8) * HC + col_l] = __floats2half2_rn(c2, c3);
        }
    }
#pragma unroll
    for (int o = 1; o < 4; o <<= 1) {
#pragma unroll
        for (int mf = 0; mf < 2; mf++)
#pragma unroll
            for (int rr = 0; rr < 2; rr++) {
                sdS[mf][rr] += __shfl_xor_sync(0xffffffffu, sdS[mf][rr], o);
                sdD[mf][rr] += __shfl_xor_sync(0xffffffffu, sdD[mf][rr], o);
            }
    }
    if (gx == 0) {
        int head = wn;
#pragma unroll
        for (int mf = 0; mf < 2; mf++)
#pragma unroll
            for (int rr = 0; rr < 2; rr++) {
                int gm = m0 + wm * 32 + mf * 16 + gy + rr * 8;
                if (gm < Nn) {
                    g_asrc[gm * 4 + head] = sdS[mf][rr];
                    g_adst[gm * 4 + head] = sdD[mf][rr];
                }
            }
    }
}

// ---------------- CSR build ----------------
__global__ void zero1_kernel() {
    int i = blockIdx.x * blockDim.x + threadIdx.x;
    if (i < Nn) g_deg[i] = 0;
    if (i < Gg) g_gcnt[i] = 0;
}
__global__ void count_kernel(const int* __restrict__ ei) {
    int e = blockIdx.x * blockDim.x + threadIdx.x;
    if (e >= Ee) return;
    atomicAdd(&g_deg[ei[Ee + e]], 1);
}
__global__ void scan1_kernel() {
    __shared__ int sm[1024];
    int i = blockIdx.x * 1024 + threadIdx.x;
    sm[threadIdx.x] = (i < Nn) ? g_deg[i] : 0;
    __syncthreads();
    for (int o = 512; o > 0; o >>= 1) {
        if (threadIdx.x < o) sm[threadIdx.x] += sm[threadIdx.x + o];
        __syncthreads();
    }
    if (threadIdx.x == 0) g_bsums[blockIdx.x] = sm[0];
}
__global__ void scan2_kernel() {
    if (threadIdx.x == 0) {
        int run = 0;
        for (int b = 0; b < NB_SCAN; b++) { int t = g_bsums[b]; g_bsums[b] = run; run += t; }
        g_off[Nn] = run;
    }
}
__global__ void scan3_kernel() {
    __shared__ int sm[1024];
    int i = blockIdx.x * 1024 + threadIdx.x;
    int v = (i < Nn) ? g_deg[i] : 0;
    sm[threadIdx.x] = v;
    __syncthreads();
    for (int o = 1; o < 1024; o <<= 1) {
        int t = (threadIdx.x >= o) ? sm[threadIdx.x - o] : 0;
        __syncthreads();
        sm[threadIdx.x] += t;
        __syncthreads();
    }
    if (i < Nn) {
        g_off[i] = g_bsums[blockIdx.x] + sm[threadIdx.x] - v;
        g_deg[i] = 0;   // re-zero for fill_kernel (replaces zero2)
    }
}
__global__ void fill_kernel(const int* __restrict__ ei) {
    int e = blockIdx.x * blockDim.x + threadIdx.x;
    if (e >= Ee) return;
    int src = ei[e];
    int dst = ei[Ee + e];
    int pos = g_off[dst] + atomicAdd(&g_deg[dst], 1);
    g_srcs[pos] = src;
}

// ---------------- K3: GAT aggregation, warp per destination ----------------
// pass A: fused online softmax (max+denom in one edge sweep)
// pass B: weighted fp16 gather
__global__ void gat_kernel(const float* __restrict__ bias) {
    int gw = (blockIdx.x * blockDim.x + threadIdx.x) >> 5;
    int lane = threadIdx.x & 31;
    if (gw >= Nn) return;
    int d = gw;
    int beg = g_off[d], end = g_off[d + 1];
    const float4* asrc4 = (const float4*)g_asrc;

    float4 adv = ((const float4*)g_adst)[d];
    float ad[4] = {adv.x, adv.y, adv.z, adv.w};
    float4 sv = asrc4[d];
    float slf[4];
    slf[0] = lrelu(sv.x + ad[0]); slf[1] = lrelu(sv.y + ad[1]);
    slf[2] = lrelu(sv.z + ad[2]); slf[3] = lrelu(sv.w + ad[3]);

    // pass A: online (m, d) per head. all lanes start m=slf; only lane0 counts self.
    float mx[4], den[4];
#pragma unroll
    for (int h = 0; h < 4; h++) { mx[h] = slf[h]; den[h] = (lane == 0) ? 1.f : 0.f; }
    for (int e = beg + lane; e < end; e += 32) {
        int s = g_srcs[e];
        float4 a = asrc4[s];
        float l[4] = {lrelu(a.x + ad[0]), lrelu(a.y + ad[1]),
                      lrelu(a.z + ad[2]), lrelu(a.w + ad[3])};
#pragma unroll
        for (int h = 0; h < 4; h++) {
            float nm = fmaxf(mx[h], l[h]);
            den[h] = den[h] * __expf(mx[h] - nm) + __expf(l[h] - nm);
            mx[h] = nm;
        }
    }
    // merge (m, d) across lanes
#pragma unroll
    for (int o = 16; o > 0; o >>= 1) {
#pragma unroll
        for (int h = 0; h < 4; h++) {
            float om = __shfl_xor_sync(0xffffffffu, mx[h], o);
            float od = __shfl_xor_sync(0xffffffffu, den[h], o);
            float nm = fmaxf(mx[h], om);
            den[h] = den[h] * __expf(mx[h] - nm) + od * __expf(om - nm);
            mx[h] = nm;
        }
    }
    float rden[4];
#pragma unroll
    for (int h = 0; h < 4; h++) rden[h] = 1.f / den[h];

    // pass B: fp16 gather. lane covers cols [lane*8, lane*8+8); head = lane>>3
    int hm = lane >> 3;
    float myad = ad[hm], mymx = mx[hm], myrd = rden[hm];
    float acc[8] = {0, 0, 0, 0, 0, 0, 0, 0};

    // self loop
    {
        float alpha = __expf(slf[hm] - mymx) * myrd;
        uint4 v = *(const uint4*)&g_xph[(size_t)d * HC + lane * 8];
        const __half2* hp = (const __half2*)&v;
#pragma unroll
        for (int q = 0; q < 4; q++) {
            float2 f = __half22float2(hp[q]);
            acc[q * 2] += alpha * f.x;
            acc[q * 2 + 1] += alpha * f.y;
        }
    }
    int e = beg;
    int sn = (e < end) ? g_srcs[e] : 0;
    while (e < end) {
        int s = sn;
        e++;
        if (e < end) sn = g_srcs[e];
        float ah = g_asrc[s * 4 + hm];
        float alpha = __expf(lrelu(ah + myad) - mymx) * myrd;
        uint4 v = *(const uint4*)&g_xph[(size_t)s * HC + lane * 8];
        const __half2* hp = (const __half2*)&v;
#pragma unroll
        for (int q = 0; q < 4; q++) {
            float2 f = __half22float2(hp[q]);
            acc[q * 2] += alpha * f.x;
            acc[q * 2 + 1] += alpha * f.y;
        }
    }
    // reduce over heads
#pragma unroll
    for (int j = 0; j < 8; j++) {
        acc[j] += __shfl_xor_sync(0xffffffffu, acc[j], 8);
        acc[j] += __shfl_xor_sync(0xffffffffu, acc[j], 16);
    }
    if (lane < 8) {
        float o[8];
#pragma unroll
        for (int j = 0; j < 8; j++)
            o[j] = fmaxf(acc[j] * 0.25f + bias[lane * 8 + j], 0.f);
        float4* hp = (float4*)&g_h[d * 64 + lane * 8];
        hp[0] = make_float4(o[0], o[1], o[2], o[3]);
        hp[1] = make_float4(o[4], o[5], o[6], o[7]);
    }
}

// ---------------- pool + MLP ----------------
__global__ void gcount_kernel(const int* __restrict__ batch) {
    int i = blockIdx.x * blockDim.x + threadIdx.x;
    if (i < Nn) atomicAdd(&g_gcnt[batch[i]], 1);
}
__global__ void gscan_kernel() {
    if (threadIdx.x == 0) {
        int run = 0;
        for (int b = 0; b < Gg; b++) { g_goff[b] = run; run += g_gcnt[b]; }
        g_goff[Gg] = run;
    }
}
__global__ void pool_mlp_kernel(const float* __restrict__ w1, const float* __restrict__ b1,
                                const float* __restrict__ w2, const float* __restrict__ b2,
                                float* __restrict__ y) {
    __shared__ float sg[64];
    __shared__ float red[256];
    int b = blockIdx.x;
    int tid = threadIdx.x;
    int col = tid & 63, grp = tid >> 6;
    int s0 = g_goff[b], s1 = g_goff[b + 1];
    float sum = 0.f;
    for (int r = s0 + grp; r < s1; r += 4) sum += g_h[r * 64 + col];
    red[tid] = sum;
    __syncthreads();
    if (grp == 0) {
        float tot = red[col] + red[col + 64] + red[col + 128] + red[col + 192];
        float cnt = (float)((s1 - s0) > 1 ? (s1 - s0) : 1);
        sg[col] = tot / cnt;
    }
    __syncthreads();
    float part = 0.f;
    if (tid < 64) {
        float hsum = b1[tid];
#pragma unroll
        for (int c = 0; c < 64; c++) hsum = fmaf(sg[c], w1[c * 64 + tid], hsum);
        part = fmaxf(hsum, 0.f) * w2[tid];
    }
    red[tid] = part;
    __syncthreads();
    if (tid == 0) {
        float s = b2[0];
        for (int j = 0; j < 64; j++) s += red[j];
        y[b] = 1.f / (1.f + __expf(-s));
    }
}

// ---------------- launch ----------------
extern "C" void kernel_launch(void* const* d_in, const int* in_sizes, int n_in,
                              void* d_out, int out_size) {
    const float* x       = (const float*)d_in[0];
    const float* W       = (const float*)d_in[1];
    const float* att_src = (const float*)d_in[2];
    const float* att_dst = (const float*)d_in[3];
    const float* bias    = (const float*)d_in[4];
    const float* w1      = (const float*)d_in[5];
    const float* b1      = (const float*)d_in[6];
    const float* w2      = (const float*)d_in[7];
    const float* b2      = (const float*)d_in[8];
    const int* ei        = (const int*)d_in[9];
    const int* batch     = (const int*)d_in[10];
    float* y = (float*)d_out;

    cvt_w_kernel<<<KPAD, 256>>>(W);
    gemm_kernel<<<(Nn + 127) / 128, 512>>>(x, att_src, att_dst);
    zero1_kernel<<<(Nn + 255) / 256, 256>>>();
    count_kernel<<<(Ee + 255) / 256, 256>>>(ei);
    scan1_kernel<<<NB_SCAN, 1024>>>();
    scan2_kernel<<<1, 32>>>();
    scan3_kernel<<<NB_SCAN, 1024>>>();
    fill_kernel<<<(Ee + 255) / 256, 256>>>(ei);
    gat_kernel<<<(Nn * 32 + 255) / 256, 256>>>(bias);
    gcount_kernel<<<(Nn + 255) / 256, 256>>>(batch);
    gscan_kernel<<<1, 32>>>();
    pool_mlp_kernel<<<Gg, 256>>>(w1, b1, w2, b2, y);
}